// round 1
// baseline (speedup 1.0000x reference)
#include <cuda_runtime.h>

#define N_NODES 100000
#define N_EDGES 1600000
#define DIM 128
#define HID 16
#define NCLS 40
#define BN_EPS 1e-5f

// ---------------- scratch (static device globals; no runtime allocation) ----
__device__ float g_h1[N_NODES * HID];    // x @ W1
__device__ float g_s1[N_NODES * HID];    // relu(spmm + b1)
__device__ float g_t [N_NODES * DIM];    // s1 @ W2
__device__ float g_h2[N_NODES * DIM];    // spmm + b2 (pre-BN)
__device__ float g_x [N_NODES * DIM];    // layer activation
__device__ float g_tc[N_NODES * NCLS];   // final s1 @ W2f
__device__ float g_sum[DIM];
__device__ float g_sumsq[DIM];
__device__ int   g_row_ptr[N_NODES + 1];

// ---------------- CSR row_ptr via per-node binary search on sorted row -----
__global__ void row_ptr_kernel(const int* __restrict__ row) {
    int i = blockIdx.x * blockDim.x + threadIdx.x;
    if (i > N_NODES) return;
    int lo = 0, hi = N_EDGES;
    while (lo < hi) {
        int mid = (lo + hi) >> 1;
        if (row[mid] < i) lo = mid + 1; else hi = mid;
    }
    g_row_ptr[i] = lo;
}

// ---------------- y[N,16] = x[N,128] @ W[128,16] (no bias) -----------------
__global__ void gemm_d_h(const float* __restrict__ x, const float* __restrict__ W,
                         float* __restrict__ y) {
    __shared__ float Ws[DIM * HID];
    for (int i = threadIdx.x; i < DIM * HID; i += blockDim.x) Ws[i] = W[i];
    __syncthreads();
    int n = blockIdx.x * blockDim.x + threadIdx.x;
    if (n >= N_NODES) return;
    float acc[HID];
    #pragma unroll
    for (int j = 0; j < HID; j++) acc[j] = 0.f;
    const float4* xr = reinterpret_cast<const float4*>(x + (size_t)n * DIM);
    #pragma unroll 8
    for (int d4 = 0; d4 < DIM / 4; d4++) {
        float4 v = xr[d4];
        int d = d4 * 4;
        #pragma unroll
        for (int j = 0; j < HID; j++) {
            acc[j] += v.x * Ws[(d + 0) * HID + j] + v.y * Ws[(d + 1) * HID + j]
                    + v.z * Ws[(d + 2) * HID + j] + v.w * Ws[(d + 3) * HID + j];
        }
    }
    float4* yr = reinterpret_cast<float4*>(y + (size_t)n * HID);
    #pragma unroll
    for (int j4 = 0; j4 < HID / 4; j4++)
        yr[j4] = make_float4(acc[j4*4+0], acc[j4*4+1], acc[j4*4+2], acc[j4*4+3]);
}

// ---------------- out[N,16] = relu(spmm(h[N,16]) + b) ----------------------
// one thread per (row, j)
__global__ void spmm_h_relu(const float* __restrict__ h, const float* __restrict__ vals,
                            const int* __restrict__ col, const float* __restrict__ b,
                            float* __restrict__ out) {
    int gid = blockIdx.x * blockDim.x + threadIdx.x;
    if (gid >= N_NODES * HID) return;
    int r = gid >> 4;
    int j = gid & 15;
    int e0 = g_row_ptr[r], e1 = g_row_ptr[r + 1];
    float acc = 0.f;
    for (int e = e0; e < e1; e++)
        acc += vals[e] * h[col[e] * HID + j];
    acc += b[j];
    out[gid] = fmaxf(acc, 0.f);
}

// ---------------- y[N,128] = h[N,16] @ W[16,128] (no bias) -----------------
// one thread per (node, 4-col group)
__global__ void gemm_h_d(const float* __restrict__ h, const float* __restrict__ W,
                         float* __restrict__ y) {
    __shared__ float Ws[HID * DIM];
    for (int i = threadIdx.x; i < HID * DIM; i += blockDim.x) Ws[i] = W[i];
    __syncthreads();
    int gid = blockIdx.x * blockDim.x + threadIdx.x;
    int n = gid >> 5;
    int q = gid & 31;
    if (n >= N_NODES) return;
    const float* hr = h + (size_t)n * HID;
    float4 acc = make_float4(0.f, 0.f, 0.f, 0.f);
    #pragma unroll
    for (int k = 0; k < HID; k++) {
        float hv = __ldg(hr + k);  // warp-uniform broadcast
        float4 w = *reinterpret_cast<const float4*>(&Ws[k * DIM + q * 4]);
        acc.x += hv * w.x; acc.y += hv * w.y; acc.z += hv * w.z; acc.w += hv * w.w;
    }
    reinterpret_cast<float4*>(y + (size_t)n * DIM)[q] = acc;
}

__global__ void zero_stats() {
    int i = threadIdx.x;
    if (i < DIM) { g_sum[i] = 0.f; g_sumsq[i] = 0.f; }
}

// ---------------- out[N,128] = spmm(h[N,128]) + b ; accumulate BN stats ----
// one warp per row, 4 floats/lane
__global__ void spmm_d_stats(const float* __restrict__ h, const float* __restrict__ vals,
                             const int* __restrict__ col, const float* __restrict__ b,
                             float* __restrict__ out) {
    __shared__ float s_sum[DIM];
    __shared__ float s_sq[DIM];
    int tid = threadIdx.x;
    for (int i = tid; i < DIM; i += blockDim.x) { s_sum[i] = 0.f; s_sq[i] = 0.f; }
    __syncthreads();

    int warp = (blockIdx.x * blockDim.x + tid) >> 5;
    int lane = tid & 31;
    if (warp < N_NODES) {
        int e0 = g_row_ptr[warp], e1 = g_row_ptr[warp + 1];
        float a0 = 0.f, a1 = 0.f, a2 = 0.f, a3 = 0.f;
        for (int e = e0; e < e1; e++) {
            float v = vals[e];
            const float* hr = h + (size_t)col[e] * DIM;
            a0 += v * hr[lane];
            a1 += v * hr[lane + 32];
            a2 += v * hr[lane + 64];
            a3 += v * hr[lane + 96];
        }
        a0 += b[lane]; a1 += b[lane + 32]; a2 += b[lane + 64]; a3 += b[lane + 96];
        float* orow = out + (size_t)warp * DIM;
        orow[lane] = a0; orow[lane + 32] = a1; orow[lane + 64] = a2; orow[lane + 96] = a3;
        atomicAdd(&s_sum[lane],      a0); atomicAdd(&s_sq[lane],      a0 * a0);
        atomicAdd(&s_sum[lane + 32], a1); atomicAdd(&s_sq[lane + 32], a1 * a1);
        atomicAdd(&s_sum[lane + 64], a2); atomicAdd(&s_sq[lane + 64], a2 * a2);
        atomicAdd(&s_sum[lane + 96], a3); atomicAdd(&s_sq[lane + 96], a3 * a3);
    }
    __syncthreads();
    for (int i = tid; i < DIM; i += blockDim.x) {
        atomicAdd(&g_sum[i],   s_sum[i]);
        atomicAdd(&g_sumsq[i], s_sq[i]);
    }
}

// ---------------- x = relu(batchnorm(h) * gamma + beta), float4 ------------
__global__ void bn_relu(const float4* __restrict__ hin, const float* __restrict__ gamma,
                        const float* __restrict__ beta, float4* __restrict__ xout) {
    int gid = blockIdx.x * blockDim.x + threadIdx.x;
    if (gid >= N_NODES * DIM / 4) return;
    int c = (gid & 31) * 4;
    const float inv_n = 1.f / (float)N_NODES;
    float4 v = hin[gid];
    float4 r;
    #pragma unroll
    for (int k = 0; k < 4; k++) {
        float mean = g_sum[c + k] * inv_n;
        float var  = g_sumsq[c + k] * inv_n - mean * mean;
        float scl  = rsqrtf(var + BN_EPS) * gamma[c + k];
        float* vp = (&v.x) + k;
        float  o  = (*vp - mean) * scl + beta[c + k];
        (&r.x)[k] = fmaxf(o, 0.f);
    }
    xout[gid] = r;
}

// ---------------- y[N,40] = h[N,16] @ W[16,40] (no bias) -------------------
__global__ void gemm_h_c(const float* __restrict__ h, const float* __restrict__ W,
                         float* __restrict__ y) {
    __shared__ float Ws[HID * NCLS];
    for (int i = threadIdx.x; i < HID * NCLS; i += blockDim.x) Ws[i] = W[i];
    __syncthreads();
    int gid = blockIdx.x * blockDim.x + threadIdx.x;
    if (gid >= N_NODES * NCLS) return;
    int n = gid / NCLS;
    int c = gid - n * NCLS;
    const float* hr = h + (size_t)n * HID;
    float acc = 0.f;
    #pragma unroll
    for (int k = 0; k < HID; k++) acc += hr[k] * Ws[k * NCLS + c];
    y[gid] = acc;
}

// ---------------- out[N,40] = spmm(h[N,40]) + b ----------------------------
// one warp per row
__global__ void spmm_c(const float* __restrict__ h, const float* __restrict__ vals,
                       const int* __restrict__ col, const float* __restrict__ b,
                       float* __restrict__ out) {
    int warp = (blockIdx.x * blockDim.x + threadIdx.x) >> 5;
    int lane = threadIdx.x & 31;
    if (warp >= N_NODES) return;
    int e0 = g_row_ptr[warp], e1 = g_row_ptr[warp + 1];
    float a0 = 0.f, a1 = 0.f;
    for (int e = e0; e < e1; e++) {
        float v = vals[e];
        const float* hr = h + (size_t)col[e] * NCLS;
        a0 += v * hr[lane];
        if (lane < 8) a1 += v * hr[32 + lane];
    }
    float* orow = out + (size_t)warp * NCLS;
    orow[lane] = a0 + b[lane];
    if (lane < 8) orow[32 + lane] = a1 + b[32 + lane];
}

// ============================================================================
extern "C" void kernel_launch(void* const* d_in, const int* in_sizes, int n_in,
                              void* d_out, int out_size) {
    const float* x     = (const float*)d_in[0];
    const float* vals  = (const float*)d_in[1];
    const float* W1    = (const float*)d_in[2];   // (3,128,16)
    const float* b1    = (const float*)d_in[3];   // (3,16)
    const float* W2    = (const float*)d_in[4];   // (3,16,128)
    const float* b2    = (const float*)d_in[5];   // (3,128)
    const float* gamma = (const float*)d_in[6];   // (3,128)
    const float* beta  = (const float*)d_in[7];   // (3,128)
    const float* W1f   = (const float*)d_in[8];   // (128,16)
    const float* b1f   = (const float*)d_in[9];   // (16,)
    const float* W2f   = (const float*)d_in[10];  // (16,40)
    const float* b2f   = (const float*)d_in[11];  // (40,)
    const int*   row   = (const int*)d_in[12];
    const int*   col   = (const int*)d_in[13];
    float* out = (float*)d_out;

    float *p_h1, *p_s1, *p_t, *p_h2, *p_x, *p_tc;
    cudaGetSymbolAddress((void**)&p_h1, g_h1);
    cudaGetSymbolAddress((void**)&p_s1, g_s1);
    cudaGetSymbolAddress((void**)&p_t,  g_t);
    cudaGetSymbolAddress((void**)&p_h2, g_h2);
    cudaGetSymbolAddress((void**)&p_x,  g_x);
    cudaGetSymbolAddress((void**)&p_tc, g_tc);

    const int TB = 256;
    row_ptr_kernel<<<(N_NODES + 1 + TB - 1) / TB, TB>>>(row);

    const float* xin = x;
    for (int i = 0; i < 3; i++) {
        gemm_d_h<<<(N_NODES + TB - 1) / TB, TB>>>(xin, W1 + (size_t)i * DIM * HID, p_h1);
        spmm_h_relu<<<(N_NODES * HID + TB - 1) / TB, TB>>>(p_h1, vals, col, b1 + i * HID, p_s1);
        gemm_h_d<<<(N_NODES * 32 + TB - 1) / TB, TB>>>(p_s1, W2 + (size_t)i * HID * DIM, p_t);
        zero_stats<<<1, 128>>>();
        spmm_d_stats<<<(N_NODES * 32 + TB - 1) / TB, TB>>>(p_t, vals, col, b2 + i * DIM, p_h2);
        bn_relu<<<(N_NODES * DIM / 4 + TB - 1) / TB, TB>>>(
            (const float4*)p_h2, gamma + i * DIM, beta + i * DIM, (float4*)p_x);
        xin = p_x;
    }

    // final head (no BN)
    gemm_d_h<<<(N_NODES + TB - 1) / TB, TB>>>(p_x, W1f, p_h1);
    spmm_h_relu<<<(N_NODES * HID + TB - 1) / TB, TB>>>(p_h1, vals, col, b1f, p_s1);
    gemm_h_c<<<(N_NODES * NCLS + TB - 1) / TB, TB>>>(p_s1, W2f, p_tc);
    spmm_c<<<(N_NODES * 32 + TB - 1) / TB, TB>>>(p_tc, vals, col, b2f, out);
}

// round 2
// speedup vs baseline: 1.1543x; 1.1543x over previous
#include <cuda_runtime.h>

#define N_NODES 100000
#define N_EDGES 1600000
#define DIM 128
#define HID 16
#define NCLS 40
#define BN_EPS 1e-5f

// ---------------- scratch (static device globals) ---------------------------
__device__ float  g_h1[N_NODES * HID];
__device__ float  g_s1[N_NODES * HID];
__device__ float  g_agg[N_NODES * HID];
__device__ double g_sum16[HID];
__device__ double g_M[HID * HID];
__device__ float  g_scale[DIM];
__device__ float  g_shift[DIM];
__device__ int    g_row_ptr[N_NODES + 1];

// ---------------- CSR row_ptr via binary search on sorted row ---------------
__global__ void row_ptr_kernel(const int* __restrict__ row) {
    int i = blockIdx.x * blockDim.x + threadIdx.x;
    if (i > N_NODES) return;
    int lo = 0, hi = N_EDGES;
    while (lo < hi) {
        int mid = (lo + hi) >> 1;
        if (row[mid] < i) lo = mid + 1; else hi = mid;
    }
    g_row_ptr[i] = lo;
}

// ---------------- y[N,16] = x[N,128] @ W[128,16] ----------------------------
__global__ void gemm_d_h(const float* __restrict__ x, const float* __restrict__ W,
                         float* __restrict__ y) {
    __shared__ float Ws[DIM * HID];
    for (int i = threadIdx.x; i < DIM * HID; i += blockDim.x) Ws[i] = W[i];
    __syncthreads();
    int n = blockIdx.x * blockDim.x + threadIdx.x;
    if (n >= N_NODES) return;
    float acc[HID];
    #pragma unroll
    for (int j = 0; j < HID; j++) acc[j] = 0.f;
    const float4* xr = reinterpret_cast<const float4*>(x + (size_t)n * DIM);
    #pragma unroll
    for (int d4 = 0; d4 < DIM / 4; d4++) {
        float4 xv = xr[d4];
        int d = d4 * 4;
        #pragma unroll
        for (int dd = 0; dd < 4; dd++) {
            float xd = (&xv.x)[dd];
            const float4* wr = reinterpret_cast<const float4*>(&Ws[(d + dd) * HID]);
            #pragma unroll
            for (int j4 = 0; j4 < 4; j4++) {
                float4 w = wr[j4];
                acc[j4 * 4 + 0] += xd * w.x;
                acc[j4 * 4 + 1] += xd * w.y;
                acc[j4 * 4 + 2] += xd * w.z;
                acc[j4 * 4 + 3] += xd * w.w;
            }
        }
    }
    float4* yr = reinterpret_cast<float4*>(y + (size_t)n * HID);
    #pragma unroll
    for (int j4 = 0; j4 < 4; j4++)
        yr[j4] = make_float4(acc[j4*4+0], acc[j4*4+1], acc[j4*4+2], acc[j4*4+3]);
}

// ---------------- 16-wide SpMM: out[r] = sum_e vals[e] * h[col[e]] ----------
// thread per (row, j); 16 rows per 256-thread block
template<bool RELU, bool ZERO_STATS>
__global__ void spmm16(const float* __restrict__ h, const float* __restrict__ vals,
                       const int* __restrict__ col, const float* __restrict__ bias,
                       float* __restrict__ out) {
    if (ZERO_STATS && blockIdx.x == 0) {
        int t = threadIdx.x;
        if (t < HID * HID) g_M[t] = 0.0;
        if (t < HID) g_sum16[t] = 0.0;
    }
    int t = threadIdx.x;
    int j = t & 15;
    int r = blockIdx.x * 16 + (t >> 4);
    if (r >= N_NODES) return;
    int e0 = g_row_ptr[r], e1 = g_row_ptr[r + 1];
    float acc = 0.f;
    int e = e0;
    for (; e + 4 <= e1; e += 4) {
        int   c0 = __ldg(col + e),  c1 = __ldg(col + e + 1);
        int   c2 = __ldg(col + e + 2), c3 = __ldg(col + e + 3);
        float v0 = __ldg(vals + e),  v1 = __ldg(vals + e + 1);
        float v2 = __ldg(vals + e + 2), v3 = __ldg(vals + e + 3);
        float h0 = __ldg(h + (size_t)c0 * HID + j);
        float h1v = __ldg(h + (size_t)c1 * HID + j);
        float h2v = __ldg(h + (size_t)c2 * HID + j);
        float h3v = __ldg(h + (size_t)c3 * HID + j);
        acc += v0 * h0; acc += v1 * h1v; acc += v2 * h2v; acc += v3 * h3v;
    }
    for (; e < e1; e++)
        acc += __ldg(vals + e) * __ldg(h + (size_t)__ldg(col + e) * HID + j);
    if (RELU) acc = fmaxf(acc + bias[j], 0.f);
    out[(size_t)r * HID + j] = acc;
}

// ---------------- 16-dim sufficient statistics: sum(agg), aggT @ agg --------
// half-warp per row; 250 blocks x 256 thr x 25 iters covers 100000 rows exactly
__global__ void stats16(const float* __restrict__ agg) {
    int t = threadIdx.x;
    int j = t & 15;
    int sub = t >> 4;
    double accM[HID];
    #pragma unroll
    for (int k = 0; k < HID; k++) accM[k] = 0.0;
    double accS = 0.0;
    for (int r = blockIdx.x * 16 + sub; r < N_NODES; r += gridDim.x * 16) {
        float a = agg[(size_t)r * HID + j];
        accS += (double)a;
        #pragma unroll
        for (int k = 0; k < HID; k++) {
            float ak = __shfl_sync(0xffffffffu, a, k, 16);
            accM[k] += (double)a * (double)ak;
        }
    }
    __shared__ double sAll[256 * HID];   // 32KB
    __shared__ double sS[256];
    #pragma unroll
    for (int k = 0; k < HID; k++) sAll[t * HID + k] = accM[k];
    sS[t] = accS;
    __syncthreads();
    // reducer: thread t <-> (jj = t>>4, kk = t&15)
    int jj = t >> 4, kk = t & 15;
    double s = 0.0;
    #pragma unroll
    for (int g = 0; g < 16; g++) s += sAll[(g * 16 + jj) * HID + kk];
    atomicAdd(&g_M[jj * HID + kk], s);
    if (t < HID) {
        double ss = 0.0;
        #pragma unroll
        for (int g = 0; g < 16; g++) ss += sS[g * 16 + t];
        atomicAdd(&g_sum16[t], ss);
    }
}

// ---------------- per-column BN affine from 16-dim stats --------------------
// x_c = t_c * scale_c + shift_c  where t = agg@W2 (h2 = t + b2)
__global__ void bn_prep(const float* __restrict__ W2, const float* __restrict__ b2,
                        const float* __restrict__ gamma, const float* __restrict__ beta) {
    __shared__ double Ms[HID * HID];
    __shared__ double Ss[HID];
    int t = threadIdx.x;  // 128 threads, one per column
    for (int i = t; i < HID * HID; i += 128) Ms[i] = g_M[i];
    if (t < HID) Ss[t] = g_sum16[t];
    __syncthreads();
    double w[HID];
    #pragma unroll
    for (int k = 0; k < HID; k++) w[k] = (double)W2[k * DIM + t];
    double s = 0.0;
    #pragma unroll
    for (int k = 0; k < HID; k++) s += Ss[k] * w[k];
    double q = 0.0;
    #pragma unroll
    for (int jj = 0; jj < HID; jj++) {
        double wj = w[jj];
        #pragma unroll
        for (int kk = 0; kk < HID; kk++) q += Ms[jj * HID + kk] * wj * w[kk];
    }
    const double invN = 1.0 / (double)N_NODES;
    double sn = s * invN;
    float var = (float)(q * invN - sn * sn);
    float scale = rsqrtf(var + BN_EPS) * gamma[t];
    g_scale[t] = scale;
    g_shift[t] = beta[t] - (float)sn * scale;   // b2 folded: shift applies to t=agg@W2
}

// ---------------- fused: h1 = relu(bn(agg@W2 + b2)) @ W1next ----------------
__global__ void fused_bn_gemm(const float* __restrict__ agg, const float* __restrict__ W2,
                              const float* __restrict__ W1n, float* __restrict__ y) {
    __shared__ float W2s[HID * DIM];   // 8KB
    __shared__ float W1s[DIM * HID];   // 8KB
    __shared__ float scl[DIM];
    __shared__ float sft[DIM];
    for (int i = threadIdx.x; i < HID * DIM; i += blockDim.x) {
        W2s[i] = W2[i];
        W1s[i] = W1n[i];
    }
    for (int i = threadIdx.x; i < DIM; i += blockDim.x) {
        scl[i] = g_scale[i];
        sft[i] = g_shift[i];
    }
    __syncthreads();
    int n = blockIdx.x * blockDim.x + threadIdx.x;
    if (n >= N_NODES) return;
    float a[HID];
    const float4* ar = reinterpret_cast<const float4*>(agg + (size_t)n * HID);
    #pragma unroll
    for (int k4 = 0; k4 < 4; k4++) {
        float4 v = ar[k4];
        a[k4*4+0] = v.x; a[k4*4+1] = v.y; a[k4*4+2] = v.z; a[k4*4+3] = v.w;
    }
    float acc[HID];
    #pragma unroll
    for (int j = 0; j < HID; j++) acc[j] = 0.f;
    #pragma unroll 4
    for (int cb = 0; cb < DIM; cb += 4) {
        float t0 = 0.f, t1 = 0.f, t2 = 0.f, t3 = 0.f;
        #pragma unroll
        for (int k = 0; k < HID; k++) {
            float4 w = *reinterpret_cast<const float4*>(&W2s[k * DIM + cb]);
            float ak = a[k];
            t0 += ak * w.x; t1 += ak * w.y; t2 += ak * w.z; t3 += ak * w.w;
        }
        float4 sc4 = *reinterpret_cast<const float4*>(&scl[cb]);
        float4 sf4 = *reinterpret_cast<const float4*>(&sft[cb]);
        float v0 = fmaxf(t0 * sc4.x + sf4.x, 0.f);
        float v1 = fmaxf(t1 * sc4.y + sf4.y, 0.f);
        float v2 = fmaxf(t2 * sc4.z + sf4.z, 0.f);
        float v3 = fmaxf(t3 * sc4.w + sf4.w, 0.f);
        #pragma unroll
        for (int j4 = 0; j4 < 4; j4++) {
            float4 w0 = *reinterpret_cast<const float4*>(&W1s[(cb + 0) * HID + j4 * 4]);
            float4 w1 = *reinterpret_cast<const float4*>(&W1s[(cb + 1) * HID + j4 * 4]);
            float4 w2 = *reinterpret_cast<const float4*>(&W1s[(cb + 2) * HID + j4 * 4]);
            float4 w3 = *reinterpret_cast<const float4*>(&W1s[(cb + 3) * HID + j4 * 4]);
            acc[j4*4+0] += v0 * w0.x + v1 * w1.x + v2 * w2.x + v3 * w3.x;
            acc[j4*4+1] += v0 * w0.y + v1 * w1.y + v2 * w2.y + v3 * w3.y;
            acc[j4*4+2] += v0 * w0.z + v1 * w1.z + v2 * w2.z + v3 * w3.z;
            acc[j4*4+3] += v0 * w0.w + v1 * w1.w + v2 * w2.w + v3 * w3.w;
        }
    }
    float4* yr = reinterpret_cast<float4*>(y + (size_t)n * HID);
    #pragma unroll
    for (int j4 = 0; j4 < 4; j4++)
        yr[j4] = make_float4(acc[j4*4+0], acc[j4*4+1], acc[j4*4+2], acc[j4*4+3]);
}

// ---------------- out[N,40] = agg[N,16] @ W[16,40] + b ----------------------
__global__ void out_gemm(const float* __restrict__ agg, const float* __restrict__ W,
                         const float* __restrict__ b, float* __restrict__ out) {
    __shared__ float Ws[HID * NCLS];
    __shared__ float bs[NCLS];
    for (int i = threadIdx.x; i < HID * NCLS; i += blockDim.x) Ws[i] = W[i];
    if (threadIdx.x < NCLS) bs[threadIdx.x] = b[threadIdx.x];
    __syncthreads();
    int n = blockIdx.x * blockDim.x + threadIdx.x;
    if (n >= N_NODES) return;
    float a[HID];
    const float4* ar = reinterpret_cast<const float4*>(agg + (size_t)n * HID);
    #pragma unroll
    for (int k4 = 0; k4 < 4; k4++) {
        float4 v = ar[k4];
        a[k4*4+0] = v.x; a[k4*4+1] = v.y; a[k4*4+2] = v.z; a[k4*4+3] = v.w;
    }
    float o[NCLS];
    #pragma unroll
    for (int c = 0; c < NCLS; c++) o[c] = bs[c];
    #pragma unroll
    for (int k = 0; k < HID; k++) {
        float ak = a[k];
        #pragma unroll
        for (int c = 0; c < NCLS; c++) o[c] += ak * Ws[k * NCLS + c];
    }
    float4* orow = reinterpret_cast<float4*>(out + (size_t)n * NCLS);
    #pragma unroll
    for (int c4 = 0; c4 < NCLS / 4; c4++)
        orow[c4] = make_float4(o[c4*4+0], o[c4*4+1], o[c4*4+2], o[c4*4+3]);
}

// ============================================================================
extern "C" void kernel_launch(void* const* d_in, const int* in_sizes, int n_in,
                              void* d_out, int out_size) {
    const float* x     = (const float*)d_in[0];
    const float* vals  = (const float*)d_in[1];
    const float* W1    = (const float*)d_in[2];   // (3,128,16)
    const float* b1    = (const float*)d_in[3];   // (3,16)
    const float* W2    = (const float*)d_in[4];   // (3,16,128)
    const float* b2    = (const float*)d_in[5];   // (3,128)
    const float* gamma = (const float*)d_in[6];   // (3,128)
    const float* beta  = (const float*)d_in[7];   // (3,128)
    const float* W1f   = (const float*)d_in[8];   // (128,16)
    const float* b1f   = (const float*)d_in[9];   // (16,)
    const float* W2f   = (const float*)d_in[10];  // (16,40)
    const float* b2f   = (const float*)d_in[11];  // (40,)
    const int*   row   = (const int*)d_in[12];
    const int*   col   = (const int*)d_in[13];
    float* out = (float*)d_out;

    float *p_h1, *p_s1, *p_agg;
    cudaGetSymbolAddress((void**)&p_h1,  g_h1);
    cudaGetSymbolAddress((void**)&p_s1,  g_s1);
    cudaGetSymbolAddress((void**)&p_agg, g_agg);

    const int TB = 256;
    const int NODE_BLK = (N_NODES + TB - 1) / TB;
    const int SPMM_BLK = (N_NODES + 15) / 16;

    row_ptr_kernel<<<(N_NODES + 1 + TB - 1) / TB, TB>>>(row);

    // layer 1 input transform
    gemm_d_h<<<NODE_BLK, TB>>>(x, W1, p_h1);

    for (int i = 0; i < 3; i++) {
        spmm16<true, true><<<SPMM_BLK, TB>>>(p_h1, vals, col, b1 + i * HID, p_s1);
        spmm16<false, false><<<SPMM_BLK, TB>>>(p_s1, vals, col, nullptr, p_agg);
        stats16<<<250, 256>>>(p_agg);
        bn_prep<<<1, 128>>>(W2 + (size_t)i * HID * DIM, b2 + i * DIM,
                            gamma + i * DIM, beta + i * DIM);
        const float* Wnext = (i < 2) ? (W1 + (size_t)(i + 1) * DIM * HID) : W1f;
        fused_bn_gemm<<<NODE_BLK, TB>>>(p_agg, W2 + (size_t)i * HID * DIM, Wnext, p_h1);
    }

    // final head: logits = spmm(relu(spmm(h1f)+b1f)) @ W2f + b2f
    spmm16<true, false><<<SPMM_BLK, TB>>>(p_h1, vals, col, b1f, p_s1);
    spmm16<false, false><<<SPMM_BLK, TB>>>(p_s1, vals, col, nullptr, p_agg);
    out_gemm<<<NODE_BLK, TB>>>(p_agg, W2f, b2f, out);
}

// round 3
// speedup vs baseline: 2.1683x; 1.8786x over previous
#include <cuda_runtime.h>

#define N_NODES 100000
#define N_EDGES 1600000
#define DIM 128
#define HID 16
#define NCLS 40
#define BN_EPS 1e-5f

// ---------------- scratch (static device globals) ---------------------------
__device__ float  g_h1[N_NODES * HID];
__device__ float  g_s1[N_NODES * HID];
__device__ float  g_agg[N_NODES * HID];
__device__ double g_sum16[HID];
__device__ double g_M[HID * HID];
__device__ float  g_scale[DIM];
__device__ float  g_shift[DIM];
__device__ int    g_row_ptr[N_NODES + 1];
__device__ unsigned int g_cnt = 0;

// ---------------- CSR row_ptr via binary search on sorted row ---------------
__global__ void row_ptr_kernel(const int* __restrict__ row) {
    int i = blockIdx.x * blockDim.x + threadIdx.x;
    if (i > N_NODES) return;
    int lo = 0, hi = N_EDGES;
    while (lo < hi) {
        int mid = (lo + hi) >> 1;
        if (row[mid] < i) lo = mid + 1; else hi = mid;
    }
    g_row_ptr[i] = lo;
}

// ---------------- y[N,16] = x[N,128] @ W[128,16] ----------------------------
__global__ void gemm_d_h(const float* __restrict__ x, const float* __restrict__ W,
                         float* __restrict__ y) {
    __shared__ float Ws[DIM * HID];
    for (int i = threadIdx.x; i < DIM * HID; i += blockDim.x) Ws[i] = W[i];
    __syncthreads();
    int n = blockIdx.x * blockDim.x + threadIdx.x;
    if (n >= N_NODES) return;
    float acc[HID];
    #pragma unroll
    for (int j = 0; j < HID; j++) acc[j] = 0.f;
    const float4* xr = reinterpret_cast<const float4*>(x + (size_t)n * DIM);
    #pragma unroll
    for (int d4 = 0; d4 < DIM / 4; d4++) {
        float4 xv = xr[d4];
        int d = d4 * 4;
        #pragma unroll
        for (int dd = 0; dd < 4; dd++) {
            float xd = (&xv.x)[dd];
            const float4* wr = reinterpret_cast<const float4*>(&Ws[(d + dd) * HID]);
            #pragma unroll
            for (int j4 = 0; j4 < 4; j4++) {
                float4 w = wr[j4];
                acc[j4 * 4 + 0] += xd * w.x;
                acc[j4 * 4 + 1] += xd * w.y;
                acc[j4 * 4 + 2] += xd * w.z;
                acc[j4 * 4 + 3] += xd * w.w;
            }
        }
    }
    float4* yr = reinterpret_cast<float4*>(y + (size_t)n * HID);
    #pragma unroll
    for (int j4 = 0; j4 < 4; j4++)
        yr[j4] = make_float4(acc[j4*4+0], acc[j4*4+1], acc[j4*4+2], acc[j4*4+3]);
}

// ---------------- 16-wide SpMM: quad (4 threads) per row, float4 gathers ----
// out[r] = sum_e vals[e] * h[col[e]]  (+bias, relu optional)
template<bool RELU, bool ZERO_STATS>
__global__ void spmm16(const float4* __restrict__ h, const float* __restrict__ vals,
                       const int* __restrict__ col, const float4* __restrict__ bias4,
                       float4* __restrict__ out) {
    if (ZERO_STATS && blockIdx.x == 0) {
        int t = threadIdx.x;
        if (t < HID * HID) g_M[t] = 0.0;
        if (t < HID) g_sum16[t] = 0.0;
    }
    int t = threadIdx.x;
    int q = t & 3;
    int r = blockIdx.x * 64 + (t >> 2);
    if (r >= N_NODES) return;
    int e0 = g_row_ptr[r], e1 = g_row_ptr[r + 1];
    float4 acc = make_float4(0.f, 0.f, 0.f, 0.f);
    int e = e0;
    for (; e + 4 <= e1; e += 4) {
        int   c0 = col[e],     c1 = col[e + 1], c2 = col[e + 2], c3 = col[e + 3];
        float v0 = vals[e],    v1 = vals[e + 1], v2 = vals[e + 2], v3 = vals[e + 3];
        float4 h0 = h[(size_t)c0 * 4 + q];
        float4 h1 = h[(size_t)c1 * 4 + q];
        float4 h2 = h[(size_t)c2 * 4 + q];
        float4 h3 = h[(size_t)c3 * 4 + q];
        acc.x += v0 * h0.x; acc.y += v0 * h0.y; acc.z += v0 * h0.z; acc.w += v0 * h0.w;
        acc.x += v1 * h1.x; acc.y += v1 * h1.y; acc.z += v1 * h1.z; acc.w += v1 * h1.w;
        acc.x += v2 * h2.x; acc.y += v2 * h2.y; acc.z += v2 * h2.z; acc.w += v2 * h2.w;
        acc.x += v3 * h3.x; acc.y += v3 * h3.y; acc.z += v3 * h3.z; acc.w += v3 * h3.w;
    }
    for (; e < e1; e++) {
        float v = vals[e];
        float4 hv = h[(size_t)col[e] * 4 + q];
        acc.x += v * hv.x; acc.y += v * hv.y; acc.z += v * hv.z; acc.w += v * hv.w;
    }
    if (RELU) {
        float4 b = bias4[q];
        acc.x = fmaxf(acc.x + b.x, 0.f);
        acc.y = fmaxf(acc.y + b.y, 0.f);
        acc.z = fmaxf(acc.z + b.z, 0.f);
        acc.w = fmaxf(acc.w + b.w, 0.f);
    }
    out[(size_t)r * 4 + q] = acc;
}

// ---------------- 16-dim stats (float partials) + fused bn_prep epilogue ----
// 16 threads per row (shfl-shared), 250 blocks x 256 threads, strided rows.
// Last block to finish computes per-column BN scale/shift (double precision).
__global__ void stats16_bn(const float* __restrict__ agg,
                           const float* __restrict__ W2,
                           const float* __restrict__ gamma,
                           const float* __restrict__ beta) {
    int t = threadIdx.x;
    int j = t & 15;
    int sub = t >> 4;
    float accM[HID];
    #pragma unroll
    for (int k = 0; k < HID; k++) accM[k] = 0.f;
    float accS = 0.f;
    for (int r = blockIdx.x * 16 + sub; r < N_NODES; r += gridDim.x * 16) {
        float a = agg[(size_t)r * HID + j];
        accS += a;
        #pragma unroll
        for (int k = 0; k < HID; k++) {
            float ak = __shfl_sync(0xffffffffu, a, k, 16);
            accM[k] += a * ak;
        }
    }
    __shared__ float sAll[256 * HID];   // 16KB
    __shared__ float sS[256];
    #pragma unroll
    for (int k = 0; k < HID; k++) sAll[t * HID + k] = accM[k];
    sS[t] = accS;
    __syncthreads();
    int jj = t >> 4, kk = t & 15;
    double s = 0.0;
    #pragma unroll
    for (int g = 0; g < 16; g++) s += (double)sAll[(g * 16 + jj) * HID + kk];
    atomicAdd(&g_M[jj * HID + kk], s);
    if (t < HID) {
        double ss = 0.0;
        #pragma unroll
        for (int g = 0; g < 16; g++) ss += (double)sS[g * 16 + t];
        atomicAdd(&g_sum16[t], ss);
    }
    // ---- last block computes BN affine ----
    __threadfence();
    __shared__ unsigned int sIsLast;
    if (t == 0) {
        unsigned int old = atomicAdd(&g_cnt, 1u);
        sIsLast = (old == gridDim.x - 1) ? 1u : 0u;
    }
    __syncthreads();
    if (!sIsLast) return;
    __shared__ double Ms[HID * HID];
    __shared__ double Ss[HID];
    for (int i = t; i < HID * HID; i += 256) Ms[i] = g_M[i];
    if (t < HID) Ss[t] = g_sum16[t];
    __syncthreads();
    if (t < DIM) {
        double w[HID];
        #pragma unroll
        for (int k = 0; k < HID; k++) w[k] = (double)W2[k * DIM + t];
        double sm = 0.0;
        #pragma unroll
        for (int k = 0; k < HID; k++) sm += Ss[k] * w[k];
        double q = 0.0;
        #pragma unroll
        for (int a = 0; a < HID; a++) {
            double wa = w[a];
            #pragma unroll
            for (int b = 0; b < HID; b++) q += Ms[a * HID + b] * wa * w[b];
        }
        const double invN = 1.0 / (double)N_NODES;
        double sn = sm * invN;
        float var = (float)(q * invN - sn * sn);
        float scale = rsqrtf(var + BN_EPS) * gamma[t];
        g_scale[t] = scale;
        g_shift[t] = beta[t] - (float)sn * scale;   // b2 cancels in (h2-mean)
    }
    if (t == 0) g_cnt = 0;
}

// ---------------- fused: h1 = relu(bn(agg@W2 + b2)) @ W1next ----------------
__global__ void fused_bn_gemm(const float* __restrict__ agg, const float* __restrict__ W2,
                              const float* __restrict__ W1n, float* __restrict__ y) {
    __shared__ float W2s[HID * DIM];
    __shared__ float W1s[DIM * HID];
    __shared__ float scl[DIM];
    __shared__ float sft[DIM];
    for (int i = threadIdx.x; i < HID * DIM; i += blockDim.x) {
        W2s[i] = W2[i];
        W1s[i] = W1n[i];
    }
    for (int i = threadIdx.x; i < DIM; i += blockDim.x) {
        scl[i] = g_scale[i];
        sft[i] = g_shift[i];
    }
    __syncthreads();
    int n = blockIdx.x * blockDim.x + threadIdx.x;
    if (n >= N_NODES) return;
    float a[HID];
    const float4* ar = reinterpret_cast<const float4*>(agg + (size_t)n * HID);
    #pragma unroll
    for (int k4 = 0; k4 < 4; k4++) {
        float4 v = ar[k4];
        a[k4*4+0] = v.x; a[k4*4+1] = v.y; a[k4*4+2] = v.z; a[k4*4+3] = v.w;
    }
    float acc[HID];
    #pragma unroll
    for (int j = 0; j < HID; j++) acc[j] = 0.f;
    #pragma unroll 4
    for (int cb = 0; cb < DIM; cb += 4) {
        float t0 = 0.f, t1 = 0.f, t2 = 0.f, t3 = 0.f;
        #pragma unroll
        for (int k = 0; k < HID; k++) {
            float4 w = *reinterpret_cast<const float4*>(&W2s[k * DIM + cb]);
            float ak = a[k];
            t0 += ak * w.x; t1 += ak * w.y; t2 += ak * w.z; t3 += ak * w.w;
        }
        float4 sc4 = *reinterpret_cast<const float4*>(&scl[cb]);
        float4 sf4 = *reinterpret_cast<const float4*>(&sft[cb]);
        float v0 = fmaxf(t0 * sc4.x + sf4.x, 0.f);
        float v1 = fmaxf(t1 * sc4.y + sf4.y, 0.f);
        float v2 = fmaxf(t2 * sc4.z + sf4.z, 0.f);
        float v3 = fmaxf(t3 * sc4.w + sf4.w, 0.f);
        #pragma unroll
        for (int j4 = 0; j4 < 4; j4++) {
            float4 w0 = *reinterpret_cast<const float4*>(&W1s[(cb + 0) * HID + j4 * 4]);
            float4 w1 = *reinterpret_cast<const float4*>(&W1s[(cb + 1) * HID + j4 * 4]);
            float4 w2 = *reinterpret_cast<const float4*>(&W1s[(cb + 2) * HID + j4 * 4]);
            float4 w3 = *reinterpret_cast<const float4*>(&W1s[(cb + 3) * HID + j4 * 4]);
            acc[j4*4+0] += v0 * w0.x + v1 * w1.x + v2 * w2.x + v3 * w3.x;
            acc[j4*4+1] += v0 * w0.y + v1 * w1.y + v2 * w2.y + v3 * w3.y;
            acc[j4*4+2] += v0 * w0.z + v1 * w1.z + v2 * w2.z + v3 * w3.z;
            acc[j4*4+3] += v0 * w0.w + v1 * w1.w + v2 * w2.w + v3 * w3.w;
        }
    }
    float4* yr = reinterpret_cast<float4*>(y + (size_t)n * HID);
    #pragma unroll
    for (int j4 = 0; j4 < 4; j4++)
        yr[j4] = make_float4(acc[j4*4+0], acc[j4*4+1], acc[j4*4+2], acc[j4*4+3]);
}

// ---------------- out[N,40] = agg[N,16] @ W[16,40] + b ----------------------
__global__ void out_gemm(const float* __restrict__ agg, const float* __restrict__ W,
                         const float* __restrict__ b, float* __restrict__ out) {
    __shared__ float Ws[HID * NCLS];
    __shared__ float bs[NCLS];
    for (int i = threadIdx.x; i < HID * NCLS; i += blockDim.x) Ws[i] = W[i];
    if (threadIdx.x < NCLS) bs[threadIdx.x] = b[threadIdx.x];
    __syncthreads();
    int n = blockIdx.x * blockDim.x + threadIdx.x;
    if (n >= N_NODES) return;
    float a[HID];
    const float4* ar = reinterpret_cast<const float4*>(agg + (size_t)n * HID);
    #pragma unroll
    for (int k4 = 0; k4 < 4; k4++) {
        float4 v = ar[k4];
        a[k4*4+0] = v.x; a[k4*4+1] = v.y; a[k4*4+2] = v.z; a[k4*4+3] = v.w;
    }
    float o[NCLS];
    #pragma unroll
    for (int c = 0; c < NCLS; c++) o[c] = bs[c];
    #pragma unroll
    for (int k = 0; k < HID; k++) {
        float ak = a[k];
        #pragma unroll
        for (int c = 0; c < NCLS; c++) o[c] += ak * Ws[k * NCLS + c];
    }
    float4* orow = reinterpret_cast<float4*>(out + (size_t)n * NCLS);
    #pragma unroll
    for (int c4 = 0; c4 < NCLS / 4; c4++)
        orow[c4] = make_float4(o[c4*4+0], o[c4*4+1], o[c4*4+2], o[c4*4+3]);
}

// ============================================================================
extern "C" void kernel_launch(void* const* d_in, const int* in_sizes, int n_in,
                              void* d_out, int out_size) {
    const float* x     = (const float*)d_in[0];
    const float* vals  = (const float*)d_in[1];
    const float* W1    = (const float*)d_in[2];   // (3,128,16)
    const float* b1    = (const float*)d_in[3];   // (3,16)
    const float* W2    = (const float*)d_in[4];   // (3,16,128)
    const float* b2    = (const float*)d_in[5];   // (3,128)  (cancels in BN)
    const float* gamma = (const float*)d_in[6];   // (3,128)
    const float* beta  = (const float*)d_in[7];   // (3,128)
    const float* W1f   = (const float*)d_in[8];   // (128,16)
    const float* b1f   = (const float*)d_in[9];   // (16,)
    const float* W2f   = (const float*)d_in[10];  // (16,40)
    const float* b2f   = (const float*)d_in[11];  // (40,)
    const int*   row   = (const int*)d_in[12];
    const int*   col   = (const int*)d_in[13];
    float* out = (float*)d_out;
    (void)b2;

    float *p_h1, *p_s1, *p_agg;
    cudaGetSymbolAddress((void**)&p_h1,  g_h1);
    cudaGetSymbolAddress((void**)&p_s1,  g_s1);
    cudaGetSymbolAddress((void**)&p_agg, g_agg);

    const int TB = 256;
    const int NODE_BLK = (N_NODES + TB - 1) / TB;
    const int SPMM_BLK = (N_NODES + 63) / 64;

    row_ptr_kernel<<<(N_NODES + 1 + TB - 1) / TB, TB>>>(row);
    gemm_d_h<<<NODE_BLK, TB>>>(x, W1, p_h1);

    for (int i = 0; i < 3; i++) {
        spmm16<true, true><<<SPMM_BLK, TB>>>((const float4*)p_h1, vals, col,
                                             (const float4*)(b1 + i * HID), (float4*)p_s1);
        spmm16<false, false><<<SPMM_BLK, TB>>>((const float4*)p_s1, vals, col,
                                               nullptr, (float4*)p_agg);
        stats16_bn<<<250, 256>>>(p_agg, W2 + (size_t)i * HID * DIM,
                                 gamma + i * DIM, beta + i * DIM);
        const float* Wnext = (i < 2) ? (W1 + (size_t)(i + 1) * DIM * HID) : W1f;
        fused_bn_gemm<<<NODE_BLK, TB>>>(p_agg, W2 + (size_t)i * HID * DIM, Wnext, p_h1);
    }

    spmm16<true, false><<<SPMM_BLK, TB>>>((const float4*)p_h1, vals, col,
                                          (const float4*)b1f, (float4*)p_s1);
    spmm16<false, false><<<SPMM_BLK, TB>>>((const float4*)p_s1, vals, col,
                                           nullptr, (float4*)p_agg);
    out_gemm<<<NODE_BLK, TB>>>(p_agg, W2f, b2f, out);
}

// round 4
// speedup vs baseline: 2.2647x; 1.0444x over previous
#include <cuda_runtime.h>

#define N_NODES 100000
#define N_EDGES 1600000
#define DIM 128
#define HID 16
#define NCLS 40
#define BN_EPS 1e-5f

typedef unsigned long long ull;

// ---------------- f32x2 packed-math helpers (B300 FFMA2 path) --------------
__device__ __forceinline__ ull pack2(float x, float y) {
    ull r; asm("mov.b64 %0,{%1,%2};" : "=l"(r) : "f"(x), "f"(y)); return r;
}
__device__ __forceinline__ void unpack2(ull v, float& x, float& y) {
    asm("mov.b64 {%0,%1},%2;" : "=f"(x), "=f"(y) : "l"(v));
}
__device__ __forceinline__ ull fma2(ull a, ull b, ull c) {
    ull d; asm("fma.rn.f32x2 %0,%1,%2,%3;" : "=l"(d) : "l"(a), "l"(b), "l"(c)); return d;
}

// ---------------- scratch (static device globals) ---------------------------
__device__ float  g_h1[N_NODES * HID];
__device__ float  g_s1[N_NODES * HID];
__device__ float  g_agg[N_NODES * HID];
__device__ double g_sum16[HID];
__device__ double g_M[HID * HID];
__device__ float  g_scale[DIM];
__device__ float  g_shift[DIM];
__device__ int    g_row_ptr[N_NODES + 1];
__device__ unsigned int g_cnt = 0;

#define TB 256
#define NODE_BLK ((N_NODES + TB - 1) / TB)          // 391
#define RP_BLK   ((N_NODES + 1 + TB - 1) / TB)      // 391
#define SPMM_BLK ((N_NODES + 31) / 32)              // 3125

// ---------------- fused: row_ptr build + y[N,16] = x[N,128] @ W[128,16] ----
__global__ void prolog_kernel(const int* __restrict__ row, const float* __restrict__ x,
                              const float* __restrict__ W, float* __restrict__ y) {
    if (blockIdx.x >= NODE_BLK) {
        // CSR row_ptr via binary search on sorted row
        int i = (blockIdx.x - NODE_BLK) * TB + threadIdx.x;
        if (i > N_NODES) return;
        int lo = 0, hi = N_EDGES;
        while (lo < hi) {
            int mid = (lo + hi) >> 1;
            if (row[mid] < i) lo = mid + 1; else hi = mid;
        }
        g_row_ptr[i] = lo;
        return;
    }
    __shared__ __align__(16) float Ws[DIM * HID];
    for (int i = threadIdx.x; i < DIM * HID; i += TB) Ws[i] = W[i];
    __syncthreads();
    int n = blockIdx.x * TB + threadIdx.x;
    if (n >= N_NODES) return;
    ull acc2[8];
    #pragma unroll
    for (int j = 0; j < 8; j++) acc2[j] = 0ull;
    const float4* xr = reinterpret_cast<const float4*>(x + (size_t)n * DIM);
    #pragma unroll 4
    for (int d4 = 0; d4 < DIM / 4; d4++) {
        float4 xv = xr[d4];
        #pragma unroll
        for (int dd = 0; dd < 4; dd++) {
            float xd = (&xv.x)[dd];
            ull xb = pack2(xd, xd);
            const ulonglong2* wr = reinterpret_cast<const ulonglong2*>(&Ws[(d4 * 4 + dd) * HID]);
            #pragma unroll
            for (int p = 0; p < 4; p++) {
                ulonglong2 w = wr[p];
                acc2[p * 2 + 0] = fma2(xb, w.x, acc2[p * 2 + 0]);
                acc2[p * 2 + 1] = fma2(xb, w.y, acc2[p * 2 + 1]);
            }
        }
    }
    ull* yr = reinterpret_cast<ull*>(y + (size_t)n * HID);
    #pragma unroll
    for (int j = 0; j < 8; j++) yr[j] = acc2[j];
}

// ---------------- 16-wide SpMM: 8 threads/row (two quads), float4 gathers --
template<bool RELU, bool ZERO_STATS>
__global__ void spmm16(const float4* __restrict__ h, const float* __restrict__ vals,
                       const int* __restrict__ col, const float4* __restrict__ bias4,
                       float4* __restrict__ out) {
    if (ZERO_STATS && blockIdx.x == 0) {
        int t = threadIdx.x;
        if (t < HID * HID) g_M[t] = 0.0;
        if (t < HID) g_sum16[t] = 0.0;
    }
    int t = threadIdx.x;
    int q = t & 3;
    int sub = (t >> 2) & 1;
    int r = blockIdx.x * 32 + (t >> 3);
    if (r >= N_NODES) return;
    int e0 = g_row_ptr[r], e1 = g_row_ptr[r + 1];
    float4 acc = make_float4(0.f, 0.f, 0.f, 0.f);
    int e = e0 + sub * 4;
    while (e + 4 <= e1) {
        int   c0 = col[e],     c1 = col[e + 1],  c2 = col[e + 2],  c3 = col[e + 3];
        float v0 = vals[e],    v1 = vals[e + 1], v2 = vals[e + 2], v3 = vals[e + 3];
        float4 h0 = h[(size_t)c0 * 4 + q];
        float4 h1 = h[(size_t)c1 * 4 + q];
        float4 h2 = h[(size_t)c2 * 4 + q];
        float4 h3 = h[(size_t)c3 * 4 + q];
        acc.x += v0 * h0.x; acc.y += v0 * h0.y; acc.z += v0 * h0.z; acc.w += v0 * h0.w;
        acc.x += v1 * h1.x; acc.y += v1 * h1.y; acc.z += v1 * h1.z; acc.w += v1 * h1.w;
        acc.x += v2 * h2.x; acc.y += v2 * h2.y; acc.z += v2 * h2.z; acc.w += v2 * h2.w;
        acc.x += v3 * h3.x; acc.y += v3 * h3.y; acc.z += v3 * h3.z; acc.w += v3 * h3.w;
        e += 8;
    }
    int eend = min(e + 4, e1);
    for (; e < eend; e++) {
        float v = vals[e];
        float4 hv = h[(size_t)col[e] * 4 + q];
        acc.x += v * hv.x; acc.y += v * hv.y; acc.z += v * hv.z; acc.w += v * hv.w;
    }
    // combine the two quads of this row (lanes l <-> l^4 share a row)
    acc.x += __shfl_xor_sync(0xffffffffu, acc.x, 4);
    acc.y += __shfl_xor_sync(0xffffffffu, acc.y, 4);
    acc.z += __shfl_xor_sync(0xffffffffu, acc.z, 4);
    acc.w += __shfl_xor_sync(0xffffffffu, acc.w, 4);
    if (sub == 0) {
        if (RELU) {
            float4 b = bias4[q];
            acc.x = fmaxf(acc.x + b.x, 0.f);
            acc.y = fmaxf(acc.y + b.y, 0.f);
            acc.z = fmaxf(acc.z + b.z, 0.f);
            acc.w = fmaxf(acc.w + b.w, 0.f);
        }
        out[(size_t)r * 4 + q] = acc;
    }
}

// ---------------- 16-dim stats (float partials) + fused bn_prep epilogue ----
__global__ void stats16_bn(const float* __restrict__ agg,
                           const float* __restrict__ W2,
                           const float* __restrict__ gamma,
                           const float* __restrict__ beta) {
    int t = threadIdx.x;
    int j = t & 15;
    int sub = t >> 4;
    float accM[HID];
    #pragma unroll
    for (int k = 0; k < HID; k++) accM[k] = 0.f;
    float accS = 0.f;
    for (int r = blockIdx.x * 16 + sub; r < N_NODES; r += gridDim.x * 16) {
        float a = agg[(size_t)r * HID + j];
        accS += a;
        #pragma unroll
        for (int k = 0; k < HID; k++) {
            float ak = __shfl_sync(0xffffffffu, a, k, 16);
            accM[k] += a * ak;
        }
    }
    __shared__ float sAll[256 * HID];
    __shared__ float sS[256];
    #pragma unroll
    for (int k = 0; k < HID; k++) sAll[t * HID + k] = accM[k];
    sS[t] = accS;
    __syncthreads();
    int jj = t >> 4, kk = t & 15;
    double s = 0.0;
    #pragma unroll
    for (int g = 0; g < 16; g++) s += (double)sAll[(g * 16 + jj) * HID + kk];
    atomicAdd(&g_M[jj * HID + kk], s);
    if (t < HID) {
        double ss = 0.0;
        #pragma unroll
        for (int g = 0; g < 16; g++) ss += (double)sS[g * 16 + t];
        atomicAdd(&g_sum16[t], ss);
    }
    __threadfence();
    __shared__ unsigned int sIsLast;
    if (t == 0) {
        unsigned int old = atomicAdd(&g_cnt, 1u);
        sIsLast = (old == gridDim.x - 1) ? 1u : 0u;
    }
    __syncthreads();
    if (!sIsLast) return;
    __shared__ double Ms[HID * HID];
    __shared__ double Ss[HID];
    for (int i = t; i < HID * HID; i += 256) Ms[i] = g_M[i];
    if (t < HID) Ss[t] = g_sum16[t];
    __syncthreads();
    if (t < DIM) {
        double w[HID];
        #pragma unroll
        for (int k = 0; k < HID; k++) w[k] = (double)W2[k * DIM + t];
        double sm = 0.0;
        #pragma unroll
        for (int k = 0; k < HID; k++) sm += Ss[k] * w[k];
        double q = 0.0;
        #pragma unroll
        for (int a = 0; a < HID; a++) {
            double wa = w[a];
            #pragma unroll
            for (int b = 0; b < HID; b++) q += Ms[a * HID + b] * wa * w[b];
        }
        const double invN = 1.0 / (double)N_NODES;
        double sn = sm * invN;
        float var = (float)(q * invN - sn * sn);
        float scale = rsqrtf(var + BN_EPS) * gamma[t];
        g_scale[t] = scale;
        g_shift[t] = beta[t] - (float)sn * scale;   // b2 cancels in (h2-mean)
    }
    if (t == 0) g_cnt = 0;
}

// ---------------- fused: h1 = relu(bn(agg@W2)) @ W1next  (f32x2 packed) -----
__global__ void fused_bn_gemm(const float* __restrict__ agg, const float* __restrict__ W2,
                              const float* __restrict__ W1n, float* __restrict__ y) {
    __shared__ __align__(16) float W2s[HID * DIM];
    __shared__ __align__(16) float W1s[DIM * HID];
    __shared__ __align__(16) float scl[DIM];
    __shared__ __align__(16) float sft[DIM];
    for (int i = threadIdx.x; i < HID * DIM; i += TB) {
        W2s[i] = W2[i];
        W1s[i] = W1n[i];
    }
    for (int i = threadIdx.x; i < DIM; i += TB) {
        scl[i] = g_scale[i];
        sft[i] = g_shift[i];
    }
    __syncthreads();
    int n = blockIdx.x * TB + threadIdx.x;
    if (n >= N_NODES) return;
    ull a2[HID];
    {
        const float4* ar = reinterpret_cast<const float4*>(agg + (size_t)n * HID);
        #pragma unroll
        for (int k4 = 0; k4 < 4; k4++) {
            float4 v = ar[k4];
            a2[k4*4+0] = pack2(v.x, v.x);
            a2[k4*4+1] = pack2(v.y, v.y);
            a2[k4*4+2] = pack2(v.z, v.z);
            a2[k4*4+3] = pack2(v.w, v.w);
        }
    }
    ull acc2[8];
    #pragma unroll
    for (int j = 0; j < 8; j++) acc2[j] = 0ull;
    #pragma unroll 2
    for (int cb = 0; cb < DIM; cb += 4) {
        ull t01 = 0ull, t23 = 0ull;
        const ulonglong2* w2p = reinterpret_cast<const ulonglong2*>(&W2s[cb]);
        #pragma unroll
        for (int k = 0; k < HID; k++) {
            ulonglong2 w = w2p[k * (DIM / 4)];
            t01 = fma2(a2[k], w.x, t01);
            t23 = fma2(a2[k], w.y, t23);
        }
        ulonglong2 sc = *reinterpret_cast<const ulonglong2*>(&scl[cb]);
        ulonglong2 sf = *reinterpret_cast<const ulonglong2*>(&sft[cb]);
        t01 = fma2(t01, sc.x, sf.x);
        t23 = fma2(t23, sc.y, sf.y);
        float v0, v1, v2, v3;
        unpack2(t01, v0, v1);
        unpack2(t23, v2, v3);
        v0 = fmaxf(v0, 0.f); v1 = fmaxf(v1, 0.f);
        v2 = fmaxf(v2, 0.f); v3 = fmaxf(v3, 0.f);
        ull vb[4] = { pack2(v0, v0), pack2(v1, v1), pack2(v2, v2), pack2(v3, v3) };
        #pragma unroll
        for (int c = 0; c < 4; c++) {
            const ulonglong2* w1p = reinterpret_cast<const ulonglong2*>(&W1s[(cb + c) * HID]);
            #pragma unroll
            for (int p = 0; p < 4; p++) {
                ulonglong2 w = w1p[p];
                acc2[p * 2 + 0] = fma2(vb[c], w.x, acc2[p * 2 + 0]);
                acc2[p * 2 + 1] = fma2(vb[c], w.y, acc2[p * 2 + 1]);
            }
        }
    }
    ull* yr = reinterpret_cast<ull*>(y + (size_t)n * HID);
    #pragma unroll
    for (int j = 0; j < 8; j++) yr[j] = acc2[j];
}

// ---------------- out[N,40] = agg[N,16] @ W[16,40] + b  (f32x2 packed) ------
__global__ void out_gemm(const float* __restrict__ agg, const float* __restrict__ W,
                         const float* __restrict__ b, float* __restrict__ out) {
    __shared__ __align__(16) float Ws[HID * NCLS];
    __shared__ __align__(16) float bs[NCLS];
    for (int i = threadIdx.x; i < HID * NCLS; i += TB) Ws[i] = W[i];
    if (threadIdx.x < NCLS) bs[threadIdx.x] = b[threadIdx.x];
    __syncthreads();
    int n = blockIdx.x * TB + threadIdx.x;
    if (n >= N_NODES) return;
    ull a2[HID];
    {
        const float4* ar = reinterpret_cast<const float4*>(agg + (size_t)n * HID);
        #pragma unroll
        for (int k4 = 0; k4 < 4; k4++) {
            float4 v = ar[k4];
            a2[k4*4+0] = pack2(v.x, v.x);
            a2[k4*4+1] = pack2(v.y, v.y);
            a2[k4*4+2] = pack2(v.z, v.z);
            a2[k4*4+3] = pack2(v.w, v.w);
        }
    }
    ull o2[NCLS / 2];
    const ull* bp = reinterpret_cast<const ull*>(bs);
    #pragma unroll
    for (int p = 0; p < NCLS / 2; p++) o2[p] = bp[p];
    #pragma unroll
    for (int k = 0; k < HID; k++) {
        const ull* wr = reinterpret_cast<const ull*>(&Ws[k * NCLS]);
        #pragma unroll
        for (int p = 0; p < NCLS / 2; p++)
            o2[p] = fma2(a2[k], wr[p], o2[p]);
    }
    ull* orow = reinterpret_cast<ull*>(out + (size_t)n * NCLS);
    #pragma unroll
    for (int p = 0; p < NCLS / 2; p++) orow[p] = o2[p];
}

// ============================================================================
extern "C" void kernel_launch(void* const* d_in, const int* in_sizes, int n_in,
                              void* d_out, int out_size) {
    const float* x     = (const float*)d_in[0];
    const float* vals  = (const float*)d_in[1];
    const float* W1    = (const float*)d_in[2];   // (3,128,16)
    const float* b1    = (const float*)d_in[3];   // (3,16)
    const float* W2    = (const float*)d_in[4];   // (3,16,128)
    const float* b2    = (const float*)d_in[5];   // (3,128)  (cancels in BN)
    const float* gamma = (const float*)d_in[6];   // (3,128)
    const float* beta  = (const float*)d_in[7];   // (3,128)
    const float* W1f   = (const float*)d_in[8];   // (128,16)
    const float* b1f   = (const float*)d_in[9];   // (16,)
    const float* W2f   = (const float*)d_in[10];  // (16,40)
    const float* b2f   = (const float*)d_in[11];  // (40,)
    const int*   row   = (const int*)d_in[12];
    const int*   col   = (const int*)d_in[13];
    float* out = (float*)d_out;
    (void)b2;

    float *p_h1, *p_s1, *p_agg;
    cudaGetSymbolAddress((void**)&p_h1,  g_h1);
    cudaGetSymbolAddress((void**)&p_s1,  g_s1);
    cudaGetSymbolAddress((void**)&p_agg, g_agg);

    prolog_kernel<<<NODE_BLK + RP_BLK, TB>>>(row, x, W1, p_h1);

    for (int i = 0; i < 3; i++) {
        spmm16<true, true><<<SPMM_BLK, TB>>>((const float4*)p_h1, vals, col,
                                             (const float4*)(b1 + i * HID), (float4*)p_s1);
        spmm16<false, false><<<SPMM_BLK, TB>>>((const float4*)p_s1, vals, col,
                                               nullptr, (float4*)p_agg);
        stats16_bn<<<250, 256>>>(p_agg, W2 + (size_t)i * HID * DIM,
                                 gamma + i * DIM, beta + i * DIM);
        const float* Wnext = (i < 2) ? (W1 + (size_t)(i + 1) * DIM * HID) : W1f;
        fused_bn_gemm<<<NODE_BLK, TB>>>(p_agg, W2 + (size_t)i * HID * DIM, Wnext, p_h1);
    }

    spmm16<true, false><<<SPMM_BLK, TB>>>((const float4*)p_h1, vals, col,
                                          (const float4*)b1f, (float4*)p_s1);
    spmm16<false, false><<<SPMM_BLK, TB>>>((const float4*)p_s1, vals, col,
                                           nullptr, (float4*)p_agg);
    out_gemm<<<NODE_BLK, TB>>>(p_agg, W2f, b2f, out);
}